// round 14
// baseline (speedup 1.0000x reference)
#include <cuda_runtime.h>
#include <stdint.h>

#define GRID_RES 64
#define BB 8
#define NN 4096
#define KC 37                         // 296 blocks = one 2-resident wave (512 thr)
#define CH 111                        // 37*111 = 4107 >= 4096
#define TILE 32
#define TTILES 4                      // 128 slots, pad -> mf=0 (zero contribution)
#define RF_STRIDE 66                  // 64 + 2; 8B-aligned row-pairs
#define CFD_SEG 20                    // per-segment stride (16 used + 4 pad)
#define CFD_STRIDE 168                // 8*20 + 8 pad; 16B aligned
#define SP_STRIDE 12                  // px,py,mf,pad,{y,y},{t,t}
#define PART_ELEMS (3 * 64 * 64)

// partials stored TRANSPOSED: [ch][col][row]
__device__ float g_partial[BB * KC * PART_ELEMS];
__device__ float g_density[BB * 4096];

typedef unsigned long long u64;

__device__ __forceinline__ float ex2f(float x) {
    float r;
    asm("ex2.approx.f32 %0, %1;" : "=f"(r) : "f"(x));
    return r;
}

#define FMA2(d, a, b) asm("fma.rn.f32x2 %0, %1, %2, %0;" : "+l"(d) : "l"(a), "l"(b))
#define MUL2(d, a, b) asm("mul.rn.f32x2 %0, %1, %2;" : "=l"(d) : "l"(a), "l"(b))
#define PACK2(d, f)   asm("mov.b64 %0, {%1, %1};" : "=l"(d) : "f"(f))

__global__ __launch_bounds__(512, 2)
void rbf_partial_kernel(const float* __restrict__ xc,
                        const float* __restrict__ yc,
                        const float* __restrict__ tc,
                        const int* __restrict__ mask) {
    const int b = blockIdx.y;
    const int kc = blockIdx.x;
    const int tid = threadIdx.x;

    const float CEXP = -72.13475204444817f;  // L = -50 * log2(e)
    const float STEP = 2.0f / 63.0f;
    const float TK1 = CEXP * STEP * STEP;
    const float TK2 = -2.0f * CEXP * STEP;
    const float C2 = ex2f(2.0f * CEXP * STEP * STEP);

    __shared__ float sRF[2][TILE][RF_STRIDE];   // raw wy per row (dbl-buffered)
    __shared__ float sCFd[2][TILE][CFD_STRIDE]; // duplicated {wx*mf} pairs (dbl)
    __shared__ float sP[3][TILE][SP_STRIDE];    // triple-buffered points

    // stage-B: warp w = col-quad (0..15), lane = row-pair
    // acc[ch][c] = {out[ch][2l][4w+c], out[ch][2l+1][4w+c]}
    u64 acc[3][4];
#pragma unroll
    for (int ch = 0; ch < 3; ch++)
#pragma unroll
        for (int c = 0; c < 4; c++) acc[ch][c] = 0ULL;

    const int w = tid >> 5;             // 0..15
    const int lane = tid & 31;
    const int row0 = lane << 1;
    // cols [4w, 4w+4): segment w>>1, half (w&1) within segment
    const int cfo = (w >> 1) * CFD_SEG + (w & 1) * 8;

    // stage-A: thread = (point pA 0..31, segment s8 0..7, axis)
    const int pA = tid >> 4;
    const int s8 = (tid >> 1) & 7;
    const int axisRF = ((tid & 1) == 0);
    const float gstart = -1.0f + STEP * (float)(s8 << 3);

    const int p0 = kc * CH;
    const int p1 = min(p0 + CH, NN);

// load point tile tt straight into sP slot tt%3 (no register staging)
#define LOADSTSP(tt)                                                      \
    do {                                                                  \
        if (tid < TILE && (tt) < TTILES) {                                \
            const int sp_ = (tt) % 3;                                     \
            const int n = p0 + (tt) * TILE + tid;                         \
            float px = 0.f, py = 0.f, mf = 0.f, yv = 0.f, tv = 0.f;       \
            if (n < p1) {                                                 \
                px = xc[(b * NN + n) * 2 + 0];                            \
                py = xc[(b * NN + n) * 2 + 1];                            \
                mf = (mask[b * NN + n] != 0) ? 0.0f : 1.0f;               \
                yv = yc[b * NN + n];                                      \
                tv = tc[b * NN + n];                                      \
            }                                                             \
            sP[sp_][tid][0] = px; sP[sp_][tid][1] = py;                   \
            sP[sp_][tid][2] = mf;                                         \
            sP[sp_][tid][4] = yv; sP[sp_][tid][5] = yv;                   \
            sP[sp_][tid][6] = tv; sP[sp_][tid][7] = tv;                   \
        }                                                                 \
    } while (0)

// Recurrence: w_{j+1} = w_j * t_j, t_{j+1} = t_j * C2; 2 MUFU per thread.
#define STAGE_A(tt)                                                       \
    do {                                                                  \
        const int bb_ = (tt) & 1;                                         \
        const int sp_ = (tt) % 3;                                         \
        if (axisRF) {                                                     \
            const float d0 = sP[sp_][pA][1] - gstart;                     \
            float wv = ex2f(CEXP * d0 * d0);                              \
            float tv = ex2f(TK1 + TK2 * d0);                              \
            _Pragma("unroll")                                             \
            for (int j = 0; j < 8; j++) {                                 \
                sRF[bb_][pA][(s8 << 3) + j] = wv;                         \
                wv *= tv; tv *= C2;                                       \
            }                                                             \
        } else {                                                          \
            const float d0 = sP[sp_][pA][0] - gstart;                     \
            float wv = ex2f(CEXP * d0 * d0) * sP[sp_][pA][2];  /* mf */   \
            float tv = ex2f(TK1 + TK2 * d0);                              \
            _Pragma("unroll")                                             \
            for (int j = 0; j < 8; j++) {                                 \
                u64 dd;                                                   \
                PACK2(dd, wv);                                            \
                *(u64*)&sCFd[bb_][pA][s8 * CFD_SEG + 2 * j] = dd;         \
                wv *= tv; tv *= C2;                                       \
            }                                                             \
        }                                                                 \
    } while (0)

#define STAGE_B(tt)                                                       \
    do {                                                                  \
        const int bb_ = (tt) & 1;                                         \
        const int sp_ = (tt) % 3;                                         \
        _Pragma("unroll 8")                                               \
        for (int p = 0; p < TILE; p++) {                                  \
            const float4* cf = (const float4*)&sCFd[bb_][p][cfo];         \
            const float4 f0 = cf[0];  /* broadcast across warp */         \
            const float4 f1 = cf[1];                                      \
            const u64* c01 = (const u64*)&f0;  /* {wx,wx} col pairs */    \
            const u64* c23 = (const u64*)&f1;                             \
            const u64 r0 = *(const u64*)&sRF[bb_][p][row0];  /* wy pair */\
            const u64 yp = *(const u64*)&sP[sp_][p][4];      /* {y,y} */  \
            const u64 tp = *(const u64*)&sP[sp_][p][6];      /* {t,t} */  \
            u64 r1, r2;                                                   \
            MUL2(r1, r0, yp);                                             \
            MUL2(r2, r0, tp);                                             \
            FMA2(acc[0][0], r0, c01[0]); FMA2(acc[0][1], r0, c01[1]);     \
            FMA2(acc[0][2], r0, c23[0]); FMA2(acc[0][3], r0, c23[1]);     \
            FMA2(acc[1][0], r1, c01[0]); FMA2(acc[1][1], r1, c01[1]);     \
            FMA2(acc[1][2], r1, c23[0]); FMA2(acc[1][3], r1, c23[1]);     \
            FMA2(acc[2][0], r2, c01[0]); FMA2(acc[2][1], r2, c01[1]);     \
            FMA2(acc[2][2], r2, c23[0]); FMA2(acc[2][3], r2, c23[1]);     \
        }                                                                 \
    } while (0)

    // prologue
    LOADSTSP(0);
    LOADSTSP(1);
    __syncthreads();
    STAGE_A(0);
    __syncthreads();

#pragma unroll 1
    for (int t = 0; t < TTILES; t++) {
        LOADSTSP(t + 2);               // slot (t+2)%3 — disjoint from A/B slots
        if (t + 1 < TTILES) STAGE_A(t + 1);
        STAGE_B(t);
        __syncthreads();
    }

    // epilogue into transposed partials [ch][col][row]; lanes cover 64 rows
    float* dst = &g_partial[(b * KC + kc) * PART_ELEMS];
#pragma unroll
    for (int ch = 0; ch < 3; ch++) {
#pragma unroll
        for (int c = 0; c < 4; c++) {
            *(u64*)&dst[ch * 4096 + (4 * w + c) * 64 + row0] = acc[ch][c];
        }
    }
}

// K2: density. Coalesced transposed reads; writes out (de-transposed) + scratch.
__global__ __launch_bounds__(256)
void rbf_density_kernel(float* __restrict__ out) {
    const int idx = blockIdx.x * blockDim.x + threadIdx.x;  // 128*256
    const int b = idx >> 12;
    const int gp = idx & 4095;          // gp = col*64 + row
    const int row = gp & 63;
    const int col = gp >> 6;

    const float* base = &g_partial[b * KC * PART_ELEMS] + gp;
    float s = 0.0f;
#pragma unroll
    for (int kcc = 0; kcc < KC; kcc++) s += base[kcc * PART_ELEMS];
    g_density[b * 4096 + gp] = s;
    out[b * 12288 + row * 64 + col] = s;
}

// K3: weighted channels / (density + eps). All reads coalesced.
__global__ __launch_bounds__(256)
void rbf_weighted_kernel(float* __restrict__ out) {
    const int idx = blockIdx.x * blockDim.x + threadIdx.x;  // 256*256
    const int b = idx >> 13;
    const int r = idx & 8191;
    const int ch = 1 + (r >> 12);
    const int gp = r & 4095;
    const int row = gp & 63;
    const int col = gp >> 6;

    const float* base = &g_partial[b * KC * PART_ELEMS + ch * 4096] + gp;
    float s = 0.0f;
#pragma unroll
    for (int kcc = 0; kcc < KC; kcc++) s += base[kcc * PART_ELEMS];
    const float d = g_density[b * 4096 + gp];
    out[b * 12288 + ch * 4096 + row * 64 + col] = s / (d + 1e-5f);
}

extern "C" void kernel_launch(void* const* d_in, const int* in_sizes, int n_in,
                              void* d_out, int out_size) {
    const float* xc = (const float*)d_in[0];
    const float* yc = (const float*)d_in[1];
    const float* tc = (const float*)d_in[2];
    const int* mask = (const int*)d_in[3];

    dim3 grid(KC, BB);
    rbf_partial_kernel<<<grid, 512>>>(xc, yc, tc, mask);

    rbf_density_kernel<<<128, 256>>>((float*)d_out);
    rbf_weighted_kernel<<<256, 256>>>((float*)d_out);
}

// round 15
// speedup vs baseline: 1.5630x; 1.5630x over previous
#include <cuda_runtime.h>
#include <stdint.h>

#define GRID_RES 64
#define BB 8
#define NN 4096
#define KC 37                         // 296 blocks = one 2-resident wave (512 thr)
#define CH 111                        // 37*111 = 4107 >= 4096
#define TILE 32
#define TTILES 4                      // 128 slots, pad -> mf=0 (zero contribution)
#define RF_STRIDE 66                  // 64 + 2; 8B-aligned row-pairs
#define CFD_SEG 20                    // per-segment stride (16 used + 4 pad)
#define CFD_STRIDE 168                // 8*20 + 8 pad; 16B aligned
#define SP_STRIDE 12                  // px,py,mf,pad,{y,y},{t,t}
#define PART_ELEMS (3 * 64 * 64)

// partials stored TRANSPOSED: [ch][col][row]
__device__ float g_partial[BB * KC * PART_ELEMS];
__device__ float g_density[BB * 4096];

typedef unsigned long long u64;

__device__ __forceinline__ float ex2f(float x) {
    float r;
    asm("ex2.approx.f32 %0, %1;" : "=f"(r) : "f"(x));
    return r;
}

#define FMA2(d, a, b) asm("fma.rn.f32x2 %0, %1, %2, %0;" : "+l"(d) : "l"(a), "l"(b))
#define MUL2(d, a, b) asm("mul.rn.f32x2 %0, %1, %2;" : "=l"(d) : "l"(a), "l"(b))
#define PACK2(d, f)   asm("mov.b64 %0, {%1, %1};" : "=l"(d) : "f"(f))

__global__ __launch_bounds__(512, 2)
void rbf_partial_kernel(const float* __restrict__ xc,
                        const float* __restrict__ yc,
                        const float* __restrict__ tc,
                        const int* __restrict__ mask) {
    const int b = blockIdx.y;
    const int kc = blockIdx.x;
    const int tid = threadIdx.x;

    const float CEXP = -72.13475204444817f;  // L = -50 * log2(e)
    const float STEP = 2.0f / 63.0f;
    const float TK1 = CEXP * STEP * STEP;
    const float TK2 = -2.0f * CEXP * STEP;
    const float C2 = ex2f(2.0f * CEXP * STEP * STEP);

    __shared__ float sRF[2][TILE][RF_STRIDE];   // raw wy per row (dbl-buffered)
    __shared__ float sCFd[2][TILE][CFD_STRIDE]; // duplicated {wx*mf} pairs (dbl)
    __shared__ float sP[3][TILE][SP_STRIDE];    // triple-buffered points

    // stage-B: warp w = col-quad (0..15), lane = row-pair
    // acc[ch][c] = {out[ch][2l][4w+c], out[ch][2l+1][4w+c]}
    u64 acc[3][4];
#pragma unroll
    for (int ch = 0; ch < 3; ch++)
#pragma unroll
        for (int c = 0; c < 4; c++) acc[ch][c] = 0ULL;

    const int w = tid >> 5;             // 0..15
    const int lane = tid & 31;
    const int row0 = lane << 1;
    // cols [4w, 4w+4): segment w>>1, half (w&1) within segment
    const int cfo = (w >> 1) * CFD_SEG + (w & 1) * 8;

    // stage-A: thread = (point pA 0..31, segment s8 0..7, axis)
    const int pA = tid >> 4;
    const int s8 = (tid >> 1) & 7;
    const int axisRF = ((tid & 1) == 0);
    const float gstart = -1.0f + STEP * (float)(s8 << 3);

    const int p0 = kc * CH;
    const int p1 = min(p0 + CH, NN);

// load point tile tt straight into sP slot tt%3 (no register staging)
#define LOADSTSP(tt)                                                      \
    do {                                                                  \
        if (tid < TILE && (tt) < TTILES) {                                \
            const int sp_ = (tt) % 3;                                     \
            const int n = p0 + (tt) * TILE + tid;                         \
            float px = 0.f, py = 0.f, mf = 0.f, yv = 0.f, tv = 0.f;       \
            if (n < p1) {                                                 \
                px = xc[(b * NN + n) * 2 + 0];                            \
                py = xc[(b * NN + n) * 2 + 1];                            \
                mf = (mask[b * NN + n] != 0) ? 0.0f : 1.0f;               \
                yv = yc[b * NN + n];                                      \
                tv = tc[b * NN + n];                                      \
            }                                                             \
            sP[sp_][tid][0] = px; sP[sp_][tid][1] = py;                   \
            sP[sp_][tid][2] = mf;                                         \
            sP[sp_][tid][4] = yv; sP[sp_][tid][5] = yv;                   \
            sP[sp_][tid][6] = tv; sP[sp_][tid][7] = tv;                   \
        }                                                                 \
    } while (0)

// Recurrence: w_{j+1} = w_j * t_j, t_{j+1} = t_j * C2; 2 MUFU per thread.
#define STAGE_A(tt)                                                       \
    do {                                                                  \
        const int bb_ = (tt) & 1;                                         \
        const int sp_ = (tt) % 3;                                         \
        if (axisRF) {                                                     \
            const float d0 = sP[sp_][pA][1] - gstart;                     \
            float wv = ex2f(CEXP * d0 * d0);                              \
            float tv = ex2f(TK1 + TK2 * d0);                              \
            _Pragma("unroll")                                             \
            for (int j = 0; j < 8; j++) {                                 \
                sRF[bb_][pA][(s8 << 3) + j] = wv;                         \
                wv *= tv; tv *= C2;                                       \
            }                                                             \
        } else {                                                          \
            const float d0 = sP[sp_][pA][0] - gstart;                     \
            float wv = ex2f(CEXP * d0 * d0) * sP[sp_][pA][2];  /* mf */   \
            float tv = ex2f(TK1 + TK2 * d0);                              \
            _Pragma("unroll")                                             \
            for (int j = 0; j < 8; j++) {                                 \
                u64 dd;                                                   \
                PACK2(dd, wv);                                            \
                *(u64*)&sCFd[bb_][pA][s8 * CFD_SEG + 2 * j] = dd;         \
                wv *= tv; tv *= C2;                                       \
            }                                                             \
        }                                                                 \
    } while (0)

#define STAGE_B(tt)                                                       \
    do {                                                                  \
        const int bb_ = (tt) & 1;                                         \
        const int sp_ = (tt) % 3;                                         \
        _Pragma("unroll 8")                                               \
        for (int p = 0; p < TILE; p++) {                                  \
            const float4* cf = (const float4*)&sCFd[bb_][p][cfo];         \
            const float4 f0 = cf[0];  /* broadcast across warp */         \
            const float4 f1 = cf[1];                                      \
            const u64* c01 = (const u64*)&f0;  /* {wx,wx} col pairs */    \
            const u64* c23 = (const u64*)&f1;                             \
            const u64 r0 = *(const u64*)&sRF[bb_][p][row0];  /* wy pair */\
            const u64 yp = *(const u64*)&sP[sp_][p][4];      /* {y,y} */  \
            const u64 tp = *(const u64*)&sP[sp_][p][6];      /* {t,t} */  \
            u64 r1, r2;                                                   \
            MUL2(r1, r0, yp);                                             \
            MUL2(r2, r0, tp);                                             \
            FMA2(acc[0][0], r0, c01[0]); FMA2(acc[0][1], r0, c01[1]);     \
            FMA2(acc[0][2], r0, c23[0]); FMA2(acc[0][3], r0, c23[1]);     \
            FMA2(acc[1][0], r1, c01[0]); FMA2(acc[1][1], r1, c01[1]);     \
            FMA2(acc[1][2], r1, c23[0]); FMA2(acc[1][3], r1, c23[1]);     \
            FMA2(acc[2][0], r2, c01[0]); FMA2(acc[2][1], r2, c01[1]);     \
            FMA2(acc[2][2], r2, c23[0]); FMA2(acc[2][3], r2, c23[1]);     \
        }                                                                 \
    } while (0)

    // prologue
    LOADSTSP(0);
    LOADSTSP(1);
    __syncthreads();
    STAGE_A(0);
    __syncthreads();

#pragma unroll 1
    for (int t = 0; t < TTILES; t++) {
        LOADSTSP(t + 2);               // slot (t+2)%3 — disjoint from A/B slots
        if (t + 1 < TTILES) STAGE_A(t + 1);
        STAGE_B(t);
        __syncthreads();
    }

    // epilogue into transposed partials [ch][col][row]; lanes cover 64 rows
    float* dst = &g_partial[(b * KC + kc) * PART_ELEMS];
#pragma unroll
    for (int ch = 0; ch < 3; ch++) {
#pragma unroll
        for (int c = 0; c < 4; c++) {
            *(u64*)&dst[ch * 4096 + (4 * w + c) * 64 + row0] = acc[ch][c];
        }
    }
}

// K2: density. Coalesced transposed reads; writes out (de-transposed) + scratch.
__global__ __launch_bounds__(256)
void rbf_density_kernel(float* __restrict__ out) {
    const int idx = blockIdx.x * blockDim.x + threadIdx.x;  // 128*256
    const int b = idx >> 12;
    const int gp = idx & 4095;          // gp = col*64 + row
    const int row = gp & 63;
    const int col = gp >> 6;

    const float* base = &g_partial[b * KC * PART_ELEMS] + gp;
    float s = 0.0f;
#pragma unroll
    for (int kcc = 0; kcc < KC; kcc++) s += base[kcc * PART_ELEMS];
    g_density[b * 4096 + gp] = s;
    out[b * 12288 + row * 64 + col] = s;
}

// K3: weighted channels / (density + eps). All reads coalesced.
__global__ __launch_bounds__(256)
void rbf_weighted_kernel(float* __restrict__ out) {
    const int idx = blockIdx.x * blockDim.x + threadIdx.x;  // 256*256
    const int b = idx >> 13;
    const int r = idx & 8191;
    const int ch = 1 + (r >> 12);
    const int gp = r & 4095;
    const int row = gp & 63;
    const int col = gp >> 6;

    const float* base = &g_partial[b * KC * PART_ELEMS + ch * 4096] + gp;
    float s = 0.0f;
#pragma unroll
    for (int kcc = 0; kcc < KC; kcc++) s += base[kcc * PART_ELEMS];
    const float d = g_density[b * 4096 + gp];
    out[b * 12288 + ch * 4096 + row * 64 + col] = s / (d + 1e-5f);
}

extern "C" void kernel_launch(void* const* d_in, const int* in_sizes, int n_in,
                              void* d_out, int out_size) {
    const float* xc = (const float*)d_in[0];
    const float* yc = (const float*)d_in[1];
    const float* tc = (const float*)d_in[2];
    const int* mask = (const int*)d_in[3];

    dim3 grid(KC, BB);
    rbf_partial_kernel<<<grid, 512>>>(xc, yc, tc, mask);

    rbf_density_kernel<<<128, 256>>>((float*)d_out);
    rbf_weighted_kernel<<<256, 256>>>((float*)d_out);
}